// round 4
// baseline (speedup 1.0000x reference)
#include <cuda_runtime.h>
#include <cstdint>

#define BATCH   128
#define N0      25600   // 160x160
#define N1      6400    // 80x80
#define N2      1600    // 40x40
#define NTOT    33600
#define KTOP    1000
#define NBINS   4096
#define CAND_CAP 4096
#define THREADS 1024

struct Smem {
    unsigned long long cand[CAND_CAP];   // 32768 B (8B aligned, first)
    unsigned int keys[NTOT];             // 134400 B
    unsigned int hist[NBINS];            // 16384 B
    unsigned int gsum[THREADS];          // 4096 B
    int ccount;
    int maxg;
    int tbin;
};

__global__ __launch_bounds__(THREADS, 1)
void topk_decode_kernel(const float* __restrict__ cls0,
                        const float* __restrict__ cls1,
                        const float* __restrict__ cls2,
                        const float* __restrict__ bb0,
                        const float* __restrict__ bb1,
                        const float* __restrict__ bb2,
                        float* __restrict__ out)
{
    extern __shared__ char smem_raw[];
    Smem& sm = *reinterpret_cast<Smem*>(smem_raw);
    const int b   = blockIdx.x;
    const int tid = threadIdx.x;

    // ---- init ----
    for (int i = tid; i < NBINS; i += THREADS) sm.hist[i] = 0u;
    if (tid == 0) { sm.ccount = 0; sm.maxg = 0; }
    __syncthreads();

    const float* c0 = cls0 + (size_t)b * N0;
    const float* c1 = cls1 + (size_t)b * N1;
    const float* c2 = cls2 + (size_t)b * N2;

    // ---- phase 1: load logits, order-preserving key, histogram top-12 bits ----
    for (int i = tid; i < NTOT; i += THREADS) {
        float v = (i < N0) ? c0[i]
                 : (i < N0 + N1) ? c1[i - N0]
                 : c2[i - N0 - N1];
        unsigned int bits = __float_as_uint(v);
        unsigned int key  = (bits & 0x80000000u) ? ~bits : (bits | 0x80000000u);
        sm.keys[i] = key;
        atomicAdd(&sm.hist[key >> 20], 1u);
    }
    __syncthreads();

    // ---- phase 2: suffix scan to find threshold bin ----
    // coarse: each thread owns 4 bins
    unsigned int s = sm.hist[4 * tid] + sm.hist[4 * tid + 1]
                   + sm.hist[4 * tid + 2] + sm.hist[4 * tid + 3];
    sm.gsum[tid] = s;
    __syncthreads();
    // inclusive suffix scan over 1024 coarse groups
    for (int off = 1; off < THREADS; off <<= 1) {
        unsigned int add = (tid + off < THREADS) ? sm.gsum[tid + off] : 0u;
        __syncthreads();
        sm.gsum[tid] += add;
        __syncthreads();
    }
    // largest coarse group with suffix >= K
    if (sm.gsum[tid] >= (unsigned)KTOP) atomicMax(&sm.maxg, tid);
    __syncthreads();
    if (tid == 0) {
        int G = sm.maxg;
        unsigned int c = (G + 1 < THREADS) ? sm.gsum[G + 1] : 0u;
        int T = 4 * G;
        for (int j = 3; j >= 0; j--) {
            c += sm.hist[4 * G + j];
            if (c >= (unsigned)KTOP) { T = 4 * G + j; break; }
        }
        sm.tbin = T;
    }
    __syncthreads();
    const unsigned int T = (unsigned int)sm.tbin;

    // ---- phase 3: compact candidates (key desc, idx asc via ~idx) ----
    for (int i = tid; i < NTOT; i += THREADS) {
        unsigned int key = sm.keys[i];
        if ((key >> 20) >= T) {
            int p = atomicAdd(&sm.ccount, 1);
            if (p < CAND_CAP)
                sm.cand[p] = ((unsigned long long)key << 32) |
                             (unsigned int)(~(unsigned int)i);
        }
    }
    __syncthreads();

    int M = sm.ccount; if (M > CAND_CAP) M = CAND_CAP;
    const int P = (M <= 1024) ? 1024 : (M <= 2048) ? 2048 : 4096;
    for (int i = M + tid; i < P; i += THREADS) sm.cand[i] = 0ull;  // sentinel sinks
    __syncthreads();

    // ---- phase 4: bitonic sort descending on packed 64-bit ----
    for (int k = 2; k <= P; k <<= 1) {
        for (int j = k >> 1; j > 0; j >>= 1) {
            for (int i = tid; i < P; i += THREADS) {
                int ixj = i ^ j;
                if (ixj > i) {
                    unsigned long long a  = sm.cand[i];
                    unsigned long long b2 = sm.cand[ixj];
                    bool desc = ((i & k) == 0);
                    if (desc ? (a < b2) : (a > b2)) {
                        sm.cand[i]   = b2;
                        sm.cand[ixj] = a;
                    }
                }
            }
            __syncthreads();
        }
    }

    // ---- phase 5: emit top-K (boxes then scores) ----
    float* out_boxes  = out;                            // [B, K, 4]
    float* out_scores = out + (size_t)BATCH * KTOP * 4; // [B, K, 1]

    for (int r = tid; r < KTOP; r += THREADS) {
        unsigned long long e = sm.cand[r];
        unsigned int key = (unsigned int)(e >> 32);
        unsigned int idx = ~(unsigned int)(e & 0xFFFFFFFFull);

        // invert order-preserving transform to recover logit
        float logit = (key & 0x80000000u)
                    ? __uint_as_float(key ^ 0x80000000u)
                    : __uint_as_float(~key);
        float sc = 1.0f / (1.0f + expf(-logit));
        out_scores[(size_t)b * KTOP + r] = sc;

        int jj, w, st, hw;
        const float* bb;
        if (idx < N0)           { jj = (int)idx;            w = 160; st = 8;  hw = N0; bb = bb0 + (size_t)b * 4 * N0; }
        else if (idx < N0 + N1) { jj = (int)idx - N0;       w = 80;  st = 16; hw = N1; bb = bb1 + (size_t)b * 4 * N1; }
        else                    { jj = (int)idx - N0 - N1;  w = 40;  st = 32; hw = N2; bb = bb2 + (size_t)b * 4 * N2; }

        int y = jj / w;
        int x = jj - y * w;
        float px = (float)(x * st);
        float py = (float)(y * st);

        float dl = bb[jj];
        float dt = bb[hw + jj];
        float dr = bb[2 * hw + jj];
        float db = bb[3 * hw + jj];

        float4 box = make_float4(px - dl, py - dt, px + dr, py + db);
        *reinterpret_cast<float4*>(&out_boxes[((size_t)b * KTOP + r) * 4]) = box;
    }
}

extern "C" void kernel_launch(void* const* d_in, const int* in_sizes, int n_in,
                              void* d_out, int out_size)
{
    // Sizes: cls0=3276800, bbox0=13107200, cls1=819200, bbox1=3276800,
    //        cls2=204800,  bbox2=819200. Disambiguate input ordering.
    const float *cls0, *cls1, *cls2, *b0, *b1, *b2;

    const int S_CLS0 = BATCH * N0;      // 3276800
    const int S_BB0  = BATCH * 4 * N0;  // 13107200
    const int S_CLS1 = BATCH * N1;      // 819200
    const int S_CLS2 = BATCH * N2;      // 204800

    if (n_in >= 6 && in_sizes[0] == S_CLS0 && in_sizes[1] == S_BB0) {
        // dict-insertion order: cls0, bbox0, cls1, bbox1, cls2, bbox2
        cls0 = (const float*)d_in[0]; b0 = (const float*)d_in[1];
        cls1 = (const float*)d_in[2]; b1 = (const float*)d_in[3];
        cls2 = (const float*)d_in[4]; b2 = (const float*)d_in[5];
    } else if (n_in >= 6 && in_sizes[0] == S_BB0) {
        // alphabetical order: bbox0, bbox1, bbox2, cls0, cls1, cls2
        b0   = (const float*)d_in[0]; b1   = (const float*)d_in[1];
        b2   = (const float*)d_in[2]; cls0 = (const float*)d_in[3];
        cls1 = (const float*)d_in[4]; cls2 = (const float*)d_in[5];
    } else {
        // signature order: cls0, cls1, cls2, bbox0, bbox1, bbox2
        cls0 = (const float*)d_in[0]; cls1 = (const float*)d_in[1];
        cls2 = (const float*)d_in[2]; b0   = (const float*)d_in[3];
        b1   = (const float*)d_in[4]; b2   = (const float*)d_in[5];
    }
    (void)in_sizes; (void)out_size;

    cudaFuncSetAttribute(topk_decode_kernel,
                         cudaFuncAttributeMaxDynamicSharedMemorySize,
                         (int)sizeof(Smem));

    topk_decode_kernel<<<BATCH, THREADS, sizeof(Smem)>>>(
        cls0, cls1, cls2, b0, b1, b2, (float*)d_out);
}

// round 5
// speedup vs baseline: 1.2626x; 1.2626x over previous
#include <cuda_runtime.h>
#include <cstdint>

#define BATCH   128
#define N0      25600   // 160x160
#define N1      6400    // 80x80
#define N2      1600    // 40x40
#define NTOT    33600
#define KTOP    1000
#define NBINS   4096
#define CAND_CAP 2048
#define THREADS 1024

typedef unsigned long long u64;
typedef unsigned int u32;

struct Smem {
    u64 cand[CAND_CAP];      // 16384 B (8B aligned, first)
    u32 keys[NTOT];          // 134400 B
    u32 hist[NBINS];         // 16384 B
    u32 wsum[32];
    u32 wexcl[32];
    int ccount;
    int tbin;
};

__device__ __forceinline__ u32 make_key(u32 u) {
    // order-preserving float->uint transform
    return u ^ (((u32)((int)u >> 31)) | 0x80000000u);
}

// warp-level compare-exchange via shfl.xor; element index parity given by tid&j
__device__ __forceinline__ u64 ce_shfl(u64 v, int j, bool desc, int tid) {
    u64 p = __shfl_xor_sync(0xffffffffu, v, j);
    bool keepmax = (((tid & j) == 0) == desc);
    u64 mx = v > p ? v : p;
    u64 mn = v > p ? p : v;
    return keepmax ? mx : mn;
}

__global__ __launch_bounds__(THREADS, 1)
void topk_decode_kernel(const float* __restrict__ cls0,
                        const float* __restrict__ cls1,
                        const float* __restrict__ cls2,
                        const float* __restrict__ bb0,
                        const float* __restrict__ bb1,
                        const float* __restrict__ bb2,
                        float* __restrict__ out)
{
    extern __shared__ char smem_raw[];
    Smem& sm = *reinterpret_cast<Smem*>(smem_raw);
    const int b    = blockIdx.x;
    const int tid  = threadIdx.x;
    const int lane = tid & 31;
    const int wid  = tid >> 5;

    // ---- init ----
    #pragma unroll
    for (int i = tid; i < NBINS; i += THREADS) sm.hist[i] = 0u;
    if (tid == 0) sm.ccount = 0;
    __syncthreads();

    // ---- phase 1: vectorized load, order-preserving keys, 12-bit histogram ----
    {
        uint4* k4 = reinterpret_cast<uint4*>(sm.keys);
        const float4* v0 = reinterpret_cast<const float4*>(cls0 + (size_t)b * N0);
        const float4* v1 = reinterpret_cast<const float4*>(cls1 + (size_t)b * N1);
        const float4* v2 = reinterpret_cast<const float4*>(cls2 + (size_t)b * N2);

        for (int i = tid; i < N0 / 4; i += THREADS) {
            float4 f = v0[i];
            uint4 kk;
            kk.x = make_key(__float_as_uint(f.x));
            kk.y = make_key(__float_as_uint(f.y));
            kk.z = make_key(__float_as_uint(f.z));
            kk.w = make_key(__float_as_uint(f.w));
            k4[i] = kk;
            atomicAdd(&sm.hist[kk.x >> 20], 1u);
            atomicAdd(&sm.hist[kk.y >> 20], 1u);
            atomicAdd(&sm.hist[kk.z >> 20], 1u);
            atomicAdd(&sm.hist[kk.w >> 20], 1u);
        }
        for (int i = tid; i < N1 / 4; i += THREADS) {
            float4 f = v1[i];
            uint4 kk;
            kk.x = make_key(__float_as_uint(f.x));
            kk.y = make_key(__float_as_uint(f.y));
            kk.z = make_key(__float_as_uint(f.z));
            kk.w = make_key(__float_as_uint(f.w));
            k4[N0 / 4 + i] = kk;
            atomicAdd(&sm.hist[kk.x >> 20], 1u);
            atomicAdd(&sm.hist[kk.y >> 20], 1u);
            atomicAdd(&sm.hist[kk.z >> 20], 1u);
            atomicAdd(&sm.hist[kk.w >> 20], 1u);
        }
        for (int i = tid; i < N2 / 4; i += THREADS) {
            float4 f = v2[i];
            uint4 kk;
            kk.x = make_key(__float_as_uint(f.x));
            kk.y = make_key(__float_as_uint(f.y));
            kk.z = make_key(__float_as_uint(f.z));
            kk.w = make_key(__float_as_uint(f.w));
            k4[(N0 + N1) / 4 + i] = kk;
            atomicAdd(&sm.hist[kk.x >> 20], 1u);
            atomicAdd(&sm.hist[kk.y >> 20], 1u);
            atomicAdd(&sm.hist[kk.z >> 20], 1u);
            atomicAdd(&sm.hist[kk.w >> 20], 1u);
        }
    }
    __syncthreads();

    // ---- phase 2: warp-shuffle suffix scan -> threshold bin ----
    {
        u32 h0 = sm.hist[4 * tid], h1 = sm.hist[4 * tid + 1];
        u32 h2 = sm.hist[4 * tid + 2], h3 = sm.hist[4 * tid + 3];
        u32 s4 = h0 + h1 + h2 + h3;

        // inclusive suffix scan within warp (lane i := sum of lanes i..31)
        u32 v = s4;
        #pragma unroll
        for (int off = 1; off < 32; off <<= 1) {
            u32 u = __shfl_down_sync(0xffffffffu, v, off);
            if (lane + off < 32) v += u;
        }
        if (lane == 0) sm.wsum[wid] = v;
        __syncthreads();
        if (tid < 32) {
            u32 t = sm.wsum[tid];
            u32 w = t;
            #pragma unroll
            for (int off = 1; off < 32; off <<= 1) {
                u32 u = __shfl_down_sync(0xffffffffu, w, off);
                if (tid + off < 32) w += u;
            }
            sm.wexcl[tid] = w - t;   // exclusive suffix over warps
        }
        __syncthreads();

        u32 gsuf  = v + sm.wexcl[wid];  // suffix count over coarse groups tid..1023
        u32 gnext = gsuf - s4;          // suffix starting at group tid+1
        if (gsuf >= (u32)KTOP && gnext < (u32)KTOP) {
            // unique crossing thread: walk my 4 bins from the top
            u32 c = gnext;
            int T = 4 * tid;
            c += h3; if (c >= (u32)KTOP) T = 4 * tid + 3;
            else { c += h2; if (c >= (u32)KTOP) T = 4 * tid + 2;
            else { c += h1; if (c >= (u32)KTOP) T = 4 * tid + 1;
            else { T = 4 * tid; } } }
            sm.tbin = T;
        }
        __syncthreads();
    }
    const u32 T = (u32)sm.tbin;

    // ---- phase 3: warp-aggregated compaction ----
    for (int i = tid; i < NTOT; i += THREADS) {
        u32 key = sm.keys[i];
        bool pred = (key >> 20) >= T;
        u32 mask = __ballot_sync(0xffffffffu, pred);
        int base = 0;
        if (lane == 0 && mask) base = atomicAdd(&sm.ccount, __popc(mask));
        base = __shfl_sync(0xffffffffu, base, 0);
        if (pred) {
            int p = base + __popc(mask & ((1u << lane) - 1u));
            if (p < CAND_CAP)
                sm.cand[p] = ((u64)key << 32) | (u32)(~(u32)i);
        }
    }
    __syncthreads();

    int M = sm.ccount; if (M > CAND_CAP) M = CAND_CAP;
    for (int i = M + tid; i < CAND_CAP; i += THREADS) sm.cand[i] = 0ull;
    __syncthreads();

    // ---- phase 4: hybrid register/shfl + smem bitonic sort, P=2048 desc ----
    // thread t holds elements t (reg a) and t+1024 (reg b)
    u64 a = sm.cand[tid];
    u64 bb = sm.cand[tid + 1024];

    // Phase A: k = 2..32, all j <= 16 -> pure shfl, no barriers.
    // Direction for both regs identical ((tid+1024)&k == tid&k for k<=32).
    #pragma unroll
    for (int k = 2; k <= 32; k <<= 1) {
        #pragma unroll
        for (int j = k >> 1; j >= 1; j >>= 1) {
            bool dA = ((tid & k) == 0);
            a  = ce_shfl(a,  j, dA, tid);
            bb = ce_shfl(bb, j, dA, tid);
        }
    }
    sm.cand[tid] = a;
    sm.cand[tid + 1024] = bb;
    __syncthreads();

    // Phase B: k = 64..2048. j >= 32 in smem (1 disjoint CE per thread),
    // j <= 16 in registers via shfl.
    for (int k = 64; k <= 2048; k <<= 1) {
        for (int j = k >> 1; j >= 32; j >>= 1) {
            int i   = ((tid & ~(j - 1)) << 1) | (tid & (j - 1));
            int ixj = i | j;
            bool desc = ((i & k) == 0);
            u64 x = sm.cand[i];
            u64 y = sm.cand[ixj];
            bool sw = desc ? (x < y) : (x > y);
            if (sw) { sm.cand[i] = y; sm.cand[ixj] = x; }
            __syncthreads();
        }
        a  = sm.cand[tid];
        bb = sm.cand[tid + 1024];
        bool dA = ((tid & k) == 0);
        bool dB = (((tid + 1024) & k) == 0);
        #pragma unroll
        for (int j = 16; j >= 1; j >>= 1) {
            a  = ce_shfl(a,  j, dA, tid);
            bb = ce_shfl(bb, j, dB, tid);
        }
        if (k < 2048) {
            sm.cand[tid] = a;
            sm.cand[tid + 1024] = bb;
            __syncthreads();
        }
    }
    // After k=2048: element r (rank r) lives in thread r's register `a` (r<1024).

    // ---- phase 5: emit top-K directly from registers ----
    float* out_boxes  = out;                            // [B, K, 4]
    float* out_scores = out + (size_t)BATCH * KTOP * 4; // [B, K, 1]

    if (tid < KTOP) {
        u64 e = a;
        u32 key = (u32)(e >> 32);
        u32 idx = ~(u32)(e & 0xFFFFFFFFull);

        // invert order-preserving transform to recover logit
        float logit = (key & 0x80000000u)
                    ? __uint_as_float(key ^ 0x80000000u)
                    : __uint_as_float(~key);
        float sc = 1.0f / (1.0f + expf(-logit));
        out_scores[(size_t)b * KTOP + tid] = sc;

        int jj, w, st, hw;
        const float* bp;
        if (idx < N0)           { jj = (int)idx;            w = 160; st = 8;  hw = N0; bp = bb0 + (size_t)b * 4 * N0; }
        else if (idx < N0 + N1) { jj = (int)idx - N0;       w = 80;  st = 16; hw = N1; bp = bb1 + (size_t)b * 4 * N1; }
        else                    { jj = (int)idx - N0 - N1;  w = 40;  st = 32; hw = N2; bp = bb2 + (size_t)b * 4 * N2; }

        int y = jj / w;
        int x = jj - y * w;
        float px = (float)(x * st);
        float py = (float)(y * st);

        float dl = bp[jj];
        float dt = bp[hw + jj];
        float dr = bp[2 * hw + jj];
        float db = bp[3 * hw + jj];

        float4 box = make_float4(px - dl, py - dt, px + dr, py + db);
        *reinterpret_cast<float4*>(&out_boxes[((size_t)b * KTOP + tid) * 4]) = box;
    }
}

extern "C" void kernel_launch(void* const* d_in, const int* in_sizes, int n_in,
                              void* d_out, int out_size)
{
    const float *cls0, *cls1, *cls2, *b0, *b1, *b2;

    const int S_CLS0 = BATCH * N0;      // 3276800
    const int S_BB0  = BATCH * 4 * N0;  // 13107200

    if (n_in >= 6 && in_sizes[0] == S_CLS0 && in_sizes[1] == S_BB0) {
        // dict-insertion order: cls0, bbox0, cls1, bbox1, cls2, bbox2
        cls0 = (const float*)d_in[0]; b0 = (const float*)d_in[1];
        cls1 = (const float*)d_in[2]; b1 = (const float*)d_in[3];
        cls2 = (const float*)d_in[4]; b2 = (const float*)d_in[5];
    } else if (n_in >= 6 && in_sizes[0] == S_BB0) {
        // alphabetical order: bbox0, bbox1, bbox2, cls0, cls1, cls2
        b0   = (const float*)d_in[0]; b1   = (const float*)d_in[1];
        b2   = (const float*)d_in[2]; cls0 = (const float*)d_in[3];
        cls1 = (const float*)d_in[4]; cls2 = (const float*)d_in[5];
    } else {
        // signature order: cls0, cls1, cls2, bbox0, bbox1, bbox2
        cls0 = (const float*)d_in[0]; cls1 = (const float*)d_in[1];
        cls2 = (const float*)d_in[2]; b0   = (const float*)d_in[3];
        b1   = (const float*)d_in[4]; b2   = (const float*)d_in[5];
    }
    (void)in_sizes; (void)out_size;

    cudaFuncSetAttribute(topk_decode_kernel,
                         cudaFuncAttributeMaxDynamicSharedMemorySize,
                         (int)sizeof(Smem));

    topk_decode_kernel<<<BATCH, THREADS, sizeof(Smem)>>>(
        cls0, cls1, cls2, b0, b1, b2, (float*)d_out);
}